// round 15
// baseline (speedup 1.0000x reference)
#include <cuda_runtime.h>
#include <cstdint>

#define BATCH 16
#define SEQY 2048
#define SEQX 2048
#define DIM 128
#define TN 64                   // x cols per tile
#define NT (SEQX / TN)          // 32 x-tiles
#define NYB 32                  // y-blocks per batch (64 rows each)
#define NTHREADS 128

#define PITCH 272u              // bytes per bf16 row (128 bf16 + 8 pad)
#define OFF_X0 0u
#define OFF_X1 34816u           // buf1 (also Y staging in prologue)
#define DLT_LO 17408u           // hi -> lo within a buf (64*272)
#define OFF_RED 0u
#define SM_BYTES 69632u

// pre-converted bf16 hi/lo operands, packed pairs (even d = low half)
// row layout: 16 uint4 per 128-d row (256 B), row-major
__device__ uint4 g_xhi[BATCH * SEQX * DIM / 8];
__device__ uint4 g_xlo[BATCH * SEQX * DIM / 8];
__device__ uint4 g_yhi[BATCH * SEQY * DIM / 8];
__device__ uint4 g_ylo[BATCH * SEQY * DIM / 8];
__device__ float g_partial[BATCH * NYB * DIM];
__device__ float g_ysum[BATCH * DIM];

static __device__ __forceinline__ uint32_t smem_u32_of(const void* p) {
    uint32_t a;
    asm("{ .reg .u64 t; cvta.to.shared.u64 t, %1; cvt.u32.u64 %0, t; }" : "=r"(a) : "l"(p));
    return a;
}
static __device__ __forceinline__ void sts32(uint32_t a, uint32_t v) {
    asm volatile("st.shared.b32 [%0], %1;" :: "r"(a), "r"(v));
}
static __device__ __forceinline__ float lds32f(uint32_t a) {
    float v;
    asm volatile("ld.shared.f32 %0, [%1];" : "=f"(v) : "r"(a));
    return v;
}
static __device__ __forceinline__ uint32_t hi_pack(float a, float b) {
    uint32_t r;
    asm("prmt.b32 %0, %1, %2, 0x7632;" : "=r"(r)
        : "r"(__float_as_uint(a)), "r"(__float_as_uint(b)));
    return r;
}
static __device__ __forceinline__ uint32_t lo_pack(float a, float b) {
    float ah = __uint_as_float(__float_as_uint(a) & 0xffff0000u);
    float bh = __uint_as_float(__float_as_uint(b) & 0xffff0000u);
    uint32_t r;
    asm("cvt.rn.bf16x2.f32 %0, %1, %2;" : "=r"(r) : "f"(b - bh), "f"(a - ah));
    return r;
}
static __device__ __forceinline__ uint32_t pack_f2(float lo, float hi) {
    uint32_t r;
    asm("cvt.rn.satfinite.bf16x2.f32 %0, %1, %2;" : "=r"(r) : "f"(hi), "f"(lo));
    return r;
}

#define LDSM4(R, a)                                                          \
    asm volatile("ldmatrix.sync.aligned.m8n8.x4.shared.b16 {%0,%1,%2,%3}, [%4];" \
        : "=r"((R)[0]), "=r"((R)[1]), "=r"((R)[2]), "=r"((R)[3]) : "r"(a))
#define LDSM4T(R, a)                                                         \
    asm volatile("ldmatrix.sync.aligned.m8n8.x4.trans.shared.b16 {%0,%1,%2,%3}, [%4];" \
        : "=r"((R)[0]), "=r"((R)[1]), "=r"((R)[2]), "=r"((R)[3]) : "r"(a))
#define MMA(D, A, B0, B1)                                                    \
    asm volatile("mma.sync.aligned.m16n8k16.row.col.f32.bf16.bf16.f32 "      \
        "{%0,%1,%2,%3}, {%4,%5,%6,%7}, {%8,%9}, {%0,%1,%2,%3};"              \
        : "+f"((D)[0]), "+f"((D)[1]), "+f"((D)[2]), "+f"((D)[3])             \
        : "r"((A)[0]), "r"((A)[1]), "r"((A)[2]), "r"((A)[3]),                \
          "r"(B0), "r"(B1))

#define CP16(dst, src)                                                       \
    asm volatile("cp.async.cg.shared.global [%0], [%1], 16;" :: "r"(dst), "l"(src))
#define CPCOMMIT() asm volatile("cp.async.commit_group;" ::: "memory")
#define CPWAIT0()  asm volatile("cp.async.wait_group 0;" ::: "memory")
#define CPWAIT1()  asm volatile("cp.async.wait_group 1;" ::: "memory")

// async-load one 64-row bf16 hi/lo tile (hsrc/lsrc point at the tile's row 0)
static __device__ __forceinline__ void load_tile(uint32_t buf, const uint4* hsrc,
                                                 const uint4* lsrc, int tid) {
    const int r  = tid >> 1;
    const int c0 = (tid & 1) * 8;
    const uint32_t dst = buf + (uint32_t)r * PITCH + (uint32_t)c0 * 16u;
    const uint4* hs = hsrc + r * 16 + c0;
    const uint4* ls = lsrc + r * 16 + c0;
    #pragma unroll
    for (int c = 0; c < 8; ++c) {
        CP16(dst + c * 16u,          (const void*)(hs + c));
        CP16(dst + c * 16u + DLT_LO, (const void*)(ls + c));
    }
}

// ---------------------------------------------------------------------------
// fp32 -> bf16 hi/lo pre-conversion for X and Y (8 floats / thread)
// ---------------------------------------------------------------------------
__global__ void __launch_bounds__(256) preconv_kernel(const float* __restrict__ X,
                                                      const float* __restrict__ Y)
{
    const uint32_t i = blockIdx.x * 256 + threadIdx.x;     // 0 .. 1048575
    const uint32_t half = BATCH * SEQX * DIM / 8;          // 524288
    const float4* src;
    uint4 *hd, *ld;
    uint32_t off;
    if (i < half) { src = (const float4*)X; hd = g_xhi; ld = g_xlo; off = i; }
    else          { src = (const float4*)Y; hd = g_yhi; ld = g_ylo; off = i - half; }
    float4 a  = src[2 * (size_t)off];
    float4 b2 = src[2 * (size_t)off + 1];
    uint4 h, l;
    h.x = hi_pack(a.x, a.y);  h.y = hi_pack(a.z, a.w);
    h.z = hi_pack(b2.x, b2.y); h.w = hi_pack(b2.z, b2.w);
    l.x = lo_pack(a.x, a.y);  l.y = lo_pack(a.z, a.w);
    l.z = lo_pack(b2.x, b2.y); l.w = lo_pack(b2.z, b2.w);
    hd[off] = h;
    ld[off] = l;
}

__global__ void dummy_kernel() {}

// ---------------------------------------------------------------------------
// Flash kernel: blockIdx = b*32 + yb (64 y-rows). 4 warps, each m16 x n64.
// Y fragments register-resident; X tiles via cp.async double buffer.
// ---------------------------------------------------------------------------
__global__ void __launch_bounds__(NTHREADS, 2)
attn_flash_kernel()
{
    extern __shared__ char smem[];
    const uint32_t smb = smem_u32_of(smem);
    const int tid  = threadIdx.x;
    const int lane = tid & 31;
    const int w    = tid >> 5;
    const int b    = blockIdx.x >> 5;
    const int yb   = blockIdx.x & 31;

    const uint4* xh = g_xhi + (size_t)b * SEQX * 16;
    const uint4* xl = g_xlo + (size_t)b * SEQX * 16;
    const uint4* yh = g_yhi + ((size_t)b * SEQY + yb * 64) * 16;
    const uint4* yl = g_ylo + ((size_t)b * SEQY + yb * 64) * 16;

    // prologue: X tile0 -> buf0, Y -> buf1 (async)
    load_tile(smb + OFF_X0, xh, xl, tid);
    CPCOMMIT();
    load_tile(smb + OFF_X1, yh, yl, tid);
    CPCOMMIT();
    CPWAIT0();
    __syncthreads();

    // Y fragments -> registers (constant across all tiles)
    uint32_t Yh[8][4], Yl[8][4];
    {
        const uint32_t aY = smb + OFF_X1 +
            (uint32_t)(w * 16 + (lane & 15)) * PITCH + (uint32_t)(lane >> 4) * 16u;
        #pragma unroll
        for (int ks = 0; ks < 8; ++ks) {
            LDSM4(Yh[ks], aY + ks * 32);
            LDSM4(Yl[ks], aY + ks * 32 + DLT_LO);
        }
    }
    __syncthreads();                       // buf1 free

    load_tile(smb + OFF_X1, xh + 64 * 16, xl + 64 * 16, tid);   // tile 1
    CPCOMMIT();

    const uint32_t bs_row = (uint32_t)((lane & 7) + ((lane >> 4) << 3)) * PITCH +
                            (uint32_t)(((lane >> 3) & 1) << 4);
    const uint32_t pv_row = (uint32_t)((lane & 7) + (((lane >> 3) & 1) << 3)) * PITCH +
                            (uint32_t)((lane >> 4) << 4);

    float O[16][4];
    #pragma unroll
    for (int n = 0; n < 16; ++n)
        #pragma unroll
        for (int e = 0; e < 4; ++e) O[n][e] = 0.f;
    float rs0 = 0.f, rs1 = 0.f;

    for (int t = 0; t < NT; ++t) {
        CPWAIT1();                          // tile t resident
        __syncthreads();
        const uint32_t XH = smb + ((t & 1) ? OFF_X1 : OFF_X0);

        // ---- S = Y(16) @ X(64)^T, 3-pass bf16 split, interleaved chains ----
        float S[8][4];
        #pragma unroll
        for (int n = 0; n < 8; ++n)
            #pragma unroll
            for (int e = 0; e < 4; ++e) S[n][e] = 0.f;

        #pragma unroll
        for (int ks = 0; ks < 8; ++ks) {
            #pragma unroll
            for (int qp = 0; qp < 2; ++qp) {
                uint32_t B0h[4], B1h[4], B0l[4], B1l[4];
                const uint32_t ba0 = XH + (uint32_t)(qp * 32) * PITCH + bs_row + ks * 32;
                const uint32_t ba1 = ba0 + 16 * PITCH;
                LDSM4(B0h, ba0);
                LDSM4(B1h, ba1);
                LDSM4(B0l, ba0 + DLT_LO);
                LDSM4(B1l, ba1 + DLT_LO);
                MMA(S[4*qp+0], Yh[ks], B0h[0], B0h[1]);
                MMA(S[4*qp+1], Yh[ks], B0h[2], B0h[3]);
                MMA(S[4*qp+2], Yh[ks], B1h[0], B1h[1]);
                MMA(S[4*qp+3], Yh[ks], B1h[2], B1h[3]);
                MMA(S[4*qp+0], Yh[ks], B0l[0], B0l[1]);
                MMA(S[4*qp+1], Yh[ks], B0l[2], B0l[3]);
                MMA(S[4*qp+2], Yh[ks], B1l[0], B1l[1]);
                MMA(S[4*qp+3], Yh[ks], B1l[2], B1l[3]);
                MMA(S[4*qp+0], Yl[ks], B0h[0], B0h[1]);
                MMA(S[4*qp+1], Yl[ks], B0h[2], B0h[3]);
                MMA(S[4*qp+2], Yl[ks], B1h[0], B1h[1]);
                MMA(S[4*qp+3], Yl[ks], B1h[2], B1h[3]);
            }
        }

        // ---- exp -> P hi/lo fragments, row-sum update ----
        uint32_t Phi[4][4], Plo[4][4];
        #pragma unroll
        for (int n = 0; n < 8; ++n) {
            float e0 = __expf(S[n][0]);
            float e1 = __expf(S[n][1]);
            float e2 = __expf(S[n][2]);
            float e3 = __expf(S[n][3]);
            rs0 += e0 + e1;
            rs1 += e2 + e3;
            const int j = n >> 1, h = n & 1;
            uint32_t p01 = pack_f2(e0, e1);
            uint32_t p23 = pack_f2(e2, e3);
            Phi[j][2*h]   = p01;
            Phi[j][2*h+1] = p23;
            float r0 = e0 - __uint_as_float(p01 << 16);
            float r1 = e1 - __uint_as_float(p01 & 0xffff0000u);
            float r2 = e2 - __uint_as_float(p23 << 16);
            float r3 = e3 - __uint_as_float(p23 & 0xffff0000u);
            Plo[j][2*h]   = pack_f2(r0, r1);
            Plo[j][2*h+1] = pack_f2(r2, r3);
        }

        // ---- O += Phi@Xhi + Phi@Xlo + Plo@Xhi, interleaved chains ----
        #pragma unroll
        for (int j = 0; j < 4; ++j) {
            #pragma unroll
            for (int qp = 0; qp < 4; ++qp) {
                uint32_t B0h[4], B1h[4], B0l[4], B1l[4];
                const uint32_t ba0 = XH + (uint32_t)(j * 16) * PITCH + pv_row + qp * 64;
                const uint32_t ba1 = ba0 + 32;
                LDSM4T(B0h, ba0);
                LDSM4T(B1h, ba1);
                LDSM4T(B0l, ba0 + DLT_LO);
                LDSM4T(B1l, ba1 + DLT_LO);
                MMA(O[4*qp+0], Phi[j], B0h[0], B0h[1]);
                MMA(O[4*qp+1], Phi[j], B0h[2], B0h[3]);
                MMA(O[4*qp+2], Phi[j], B1h[0], B1h[1]);
                MMA(O[4*qp+3], Phi[j], B1h[2], B1h[3]);
                MMA(O[4*qp+0], Phi[j], B0l[0], B0l[1]);
                MMA(O[4*qp+1], Phi[j], B0l[2], B0l[3]);
                MMA(O[4*qp+2], Phi[j], B1l[0], B1l[1]);
                MMA(O[4*qp+3], Phi[j], B1l[2], B1l[3]);
                MMA(O[4*qp+0], Plo[j], B0h[0], B0h[1]);
                MMA(O[4*qp+1], Plo[j], B0h[2], B0h[3]);
                MMA(O[4*qp+2], Plo[j], B1h[0], B1h[1]);
                MMA(O[4*qp+3], Plo[j], B1h[2], B1h[3]);
            }
        }
        __syncthreads();                    // buf(t) free
        if (t + 2 < NT) {
            load_tile(smb + ((t & 1) ? OFF_X1 : OFF_X0),
                      xh + (size_t)(t + 2) * 64 * 16,
                      xl + (size_t)(t + 2) * 64 * 16, tid);
            CPCOMMIT();
        }
    }

    // ---- epilogue: per-warp sum_y O/l -> smem -> g_partial ----
    rs0 += __shfl_xor_sync(0xffffffffu, rs0, 1);
    rs0 += __shfl_xor_sync(0xffffffffu, rs0, 2);
    rs1 += __shfl_xor_sync(0xffffffffu, rs1, 1);
    rs1 += __shfl_xor_sync(0xffffffffu, rs1, 2);
    const float li0 = 1.0f / rs0;
    const float li1 = 1.0f / rs1;
    #pragma unroll
    for (int n = 0; n < 16; ++n) {
        float v0 = O[n][0] * li0 + O[n][2] * li1;
        float v1 = O[n][1] * li0 + O[n][3] * li1;
        v0 += __shfl_xor_sync(0xffffffffu, v0, 4);
        v0 += __shfl_xor_sync(0xffffffffu, v0, 8);
        v0 += __shfl_xor_sync(0xffffffffu, v0, 16);
        v1 += __shfl_xor_sync(0xffffffffu, v1, 4);
        v1 += __shfl_xor_sync(0xffffffffu, v1, 8);
        v1 += __shfl_xor_sync(0xffffffffu, v1, 16);
        if (lane < 4) {
            uint32_t ra = smb + OFF_RED + (uint32_t)(w * 128 + n * 8 + lane * 2) * 4;
            sts32(ra,     __float_as_uint(v0));
            sts32(ra + 4, __float_as_uint(v1));
        }
    }
    __syncthreads();
    if (tid < DIM) {
        float s = 0.f;
        #pragma unroll
        for (int ww = 0; ww < 4; ++ww)
            s += lds32f(smb + OFF_RED + (uint32_t)(ww * 128 + tid) * 4);
        g_partial[blockIdx.x * DIM + tid] = s;
    }
}

// ---------------------------------------------------------------------------
// visual path (exact fp32 rank-1)
// ---------------------------------------------------------------------------
__global__ void ysum_kernel(const float* __restrict__ Yg)
{
    __shared__ float buf[2 * DIM];
    int b = blockIdx.x;
    int d = threadIdx.x & 127;
    int h = threadIdx.x >> 7;
    const float* p = Yg + ((size_t)b * SEQY + h) * DIM + d;
    float s0 = 0.f, s1 = 0.f, s2 = 0.f, s3 = 0.f;
    for (int y = 0; y < SEQY / 2; y += 4) {
        s0 += p[(size_t)(2 * (y + 0)) * DIM];
        s1 += p[(size_t)(2 * (y + 1)) * DIM];
        s2 += p[(size_t)(2 * (y + 2)) * DIM];
        s3 += p[(size_t)(2 * (y + 3)) * DIM];
    }
    buf[h * DIM + d] = (s0 + s1) + (s2 + s3);
    __syncthreads();
    if (h == 0) g_ysum[b * DIM + d] = buf[d] + buf[DIM + d];
}

__global__ void visual_kernel(const float* __restrict__ Xg, float* __restrict__ out)
{
    __shared__ float ys[DIM];
    const int bpb = SEQX / 8;
    int b  = blockIdx.x / bpb;
    int x0 = (blockIdx.x % bpb) * 8;
    if (threadIdx.x < DIM) ys[threadIdx.x] = g_ysum[b * DIM + threadIdx.x];
    __syncthreads();
    int w    = threadIdx.x >> 5;
    int lane = threadIdx.x & 31;
    int x    = x0 + w;
    const float* xp = Xg + ((size_t)b * SEQX + x) * DIM + lane * 4;
    float4 xv = *reinterpret_cast<const float4*>(xp);
    float4 yv = *reinterpret_cast<const float4*>(ys + lane * 4);
    float sdot = xv.x * yv.x + xv.y * yv.y + xv.z * yv.z + xv.w * yv.w;
    #pragma unroll
    for (int o = 16; o > 0; o >>= 1)
        sdot += __shfl_xor_sync(0xffffffffu, sdot, o);
    if (lane == 0) out[(size_t)b * SEQX + x] = sdot * (1.0f / SEQY);
}

__global__ void outfinal_kernel(float* __restrict__ out)
{
    int b = blockIdx.x, d = threadIdx.x;
    float s = 0.f;
    #pragma unroll
    for (int g = 0; g < NYB; ++g)
        s += g_partial[(b * NYB + g) * DIM + d];
    out[(size_t)BATCH * SEQX + b * DIM + d] = s * (1.0f / SEQY);
}

extern "C" void kernel_launch(void* const* d_in, const int* in_sizes, int n_in,
                              void* d_out, int out_size)
{
    const float* X = (const float*)d_in[0];
    const float* Y = (const float*)d_in[1];
    float* out = (float*)d_out;
    (void)in_sizes; (void)n_in; (void)out_size;

    cudaFuncSetAttribute(attn_flash_kernel,
                         cudaFuncAttributeMaxDynamicSharedMemorySize, SM_BYTES);

    // order chosen so launch #6 (ncu -s 5 -c 1) is attn_flash_kernel
    preconv_kernel<<<4096, 256>>>(X, Y);
    ysum_kernel<<<BATCH, 256>>>(Y);
    visual_kernel<<<BATCH * SEQX / 8, 256>>>(X, out);
    dummy_kernel<<<1, 32>>>();
    dummy_kernel<<<1, 32>>>();
    attn_flash_kernel<<<BATCH * NYB, NTHREADS, SM_BYTES>>>();
    outfinal_kernel<<<BATCH, DIM>>>(out);
}

// round 16
// speedup vs baseline: 1.2110x; 1.2110x over previous
#include <cuda_runtime.h>
#include <cstdint>

#define BATCH 16
#define SEQY 2048
#define SEQX 2048
#define DIM 128
#define TN 64                   // x cols per tile
#define NT (SEQX / TN)          // 32 x-tiles
#define YB (SEQY / 128)         // 16 y-blocks per batch
#define NTHREADS 256

#define PITCH 272u              // bytes per bf16 row (128 bf16 + 8 pad)

// smem layout
#define OFF_Y    0u             // Y hi (128*272) then Y lo
#define DLT_YLO  34816u
#define OFF_X0   69632u
#define OFF_X1   104448u
#define DLT_XLO  17408u         // hi -> lo within an X buf (64*272)
#define OFF_RED  OFF_X0         // reuse X buf for epilogue reduce
#define SM_BYTES 139264u

// pre-converted bf16 hi/lo operands, packed pairs (even d = low half of word)
__device__ uint4 g_xhi[BATCH * SEQX * DIM / 8];
__device__ uint4 g_xlo[BATCH * SEQX * DIM / 8];
__device__ uint4 g_yhi[BATCH * SEQY * DIM / 8];
__device__ uint4 g_ylo[BATCH * SEQY * DIM / 8];
__device__ float g_partial[BATCH * YB * DIM];
__device__ float g_ysum[BATCH * DIM];

static __device__ __forceinline__ uint32_t smem_u32_of(const void* p) {
    uint32_t a;
    asm("{ .reg .u64 t; cvta.to.shared.u64 t, %1; cvt.u32.u64 %0, t; }" : "=r"(a) : "l"(p));
    return a;
}
static __device__ __forceinline__ void sts32(uint32_t a, uint32_t v) {
    asm volatile("st.shared.b32 [%0], %1;" :: "r"(a), "r"(v));
}
static __device__ __forceinline__ float lds32f(uint32_t a) {
    float v;
    asm volatile("ld.shared.f32 %0, [%1];" : "=f"(v) : "r"(a));
    return v;
}
static __device__ __forceinline__ uint32_t hi_pack(float a, float b) {
    uint32_t r;
    asm("prmt.b32 %0, %1, %2, 0x7632;" : "=r"(r)
        : "r"(__float_as_uint(a)), "r"(__float_as_uint(b)));
    return r;
}
static __device__ __forceinline__ uint32_t lo_pack(float a, float b) {
    float ah = __uint_as_float(__float_as_uint(a) & 0xffff0000u);
    float bh = __uint_as_float(__float_as_uint(b) & 0xffff0000u);
    uint32_t r;
    asm("cvt.rn.bf16x2.f32 %0, %1, %2;" : "=r"(r) : "f"(b - bh), "f"(a - ah));
    return r;
}
static __device__ __forceinline__ uint32_t pack_f2(float lo, float hi) {
    uint32_t r;
    asm("cvt.rn.satfinite.bf16x2.f32 %0, %1, %2;" : "=r"(r) : "f"(hi), "f"(lo));
    return r;
}

#define LDSM4(R, a)                                                          \
    asm volatile("ldmatrix.sync.aligned.m8n8.x4.shared.b16 {%0,%1,%2,%3}, [%4];" \
        : "=r"((R)[0]), "=r"((R)[1]), "=r"((R)[2]), "=r"((R)[3]) : "r"(a))
#define LDSM4T(R, a)                                                         \
    asm volatile("ldmatrix.sync.aligned.m8n8.x4.trans.shared.b16 {%0,%1,%2,%3}, [%4];" \
        : "=r"((R)[0]), "=r"((R)[1]), "=r"((R)[2]), "=r"((R)[3]) : "r"(a))
#define MMA(D, A, B0, B1)                                                    \
    asm volatile("mma.sync.aligned.m16n8k16.row.col.f32.bf16.bf16.f32 "      \
        "{%0,%1,%2,%3}, {%4,%5,%6,%7}, {%8,%9}, {%0,%1,%2,%3};"              \
        : "+f"((D)[0]), "+f"((D)[1]), "+f"((D)[2]), "+f"((D)[3])             \
        : "r"((A)[0]), "r"((A)[1]), "r"((A)[2]), "r"((A)[3]),                \
          "r"(B0), "r"(B1))

#define CP16(dst, src)                                                       \
    asm volatile("cp.async.cg.shared.global [%0], [%1], 16;" :: "r"(dst), "l"(src))
#define CPCOMMIT() asm volatile("cp.async.commit_group;" ::: "memory")
#define CPWAIT0()  asm volatile("cp.async.wait_group 0;" ::: "memory")
#define CPWAIT1()  asm volatile("cp.async.wait_group 1;" ::: "memory")

// async-load one 64-row X tile (hi+lo), 256 threads, 8 x 16B per thread
static __device__ __forceinline__ void load_xtile(uint32_t buf, const uint4* hs,
                                                  const uint4* ls, int tid) {
    const int r  = tid >> 2;             // 0..63
    const int c0 = (tid & 3) * 4;        // uint4 col 0..15
    const uint32_t dst = buf + (uint32_t)r * PITCH + (uint32_t)c0 * 16u;
    const uint4* h = hs + r * 16 + c0;
    const uint4* l = ls + r * 16 + c0;
    #pragma unroll
    for (int c = 0; c < 4; ++c) {
        CP16(dst + c * 16u,           (const void*)(h + c));
        CP16(dst + c * 16u + DLT_XLO, (const void*)(l + c));
    }
}

// ---------------------------------------------------------------------------
// fp32 -> bf16 hi/lo pre-conversion for X and Y
// ---------------------------------------------------------------------------
__global__ void __launch_bounds__(256) preconv_kernel(const float* __restrict__ X,
                                                      const float* __restrict__ Y)
{
    const uint32_t i = blockIdx.x * 256 + threadIdx.x;
    const uint32_t half = BATCH * SEQX * DIM / 8;
    const float4* src;
    uint4 *hd, *ld;
    uint32_t off;
    if (i < half) { src = (const float4*)X; hd = g_xhi; ld = g_xlo; off = i; }
    else          { src = (const float4*)Y; hd = g_yhi; ld = g_ylo; off = i - half; }
    float4 a  = src[2 * (size_t)off];
    float4 b2 = src[2 * (size_t)off + 1];
    uint4 h, l;
    h.x = hi_pack(a.x, a.y);   h.y = hi_pack(a.z, a.w);
    h.z = hi_pack(b2.x, b2.y); h.w = hi_pack(b2.z, b2.w);
    l.x = lo_pack(a.x, a.y);   l.y = lo_pack(a.z, a.w);
    l.z = lo_pack(b2.x, b2.y); l.w = lo_pack(b2.z, b2.w);
    hd[off] = h;
    ld[off] = l;
}

// ---------------------------------------------------------------------------
// Flash kernel: blockIdx = b*16 + yb (128 y-rows). 8 warps, each m16 x n64.
// Y in smem (hi/lo), X double-buffered via cp.async, O register-resident.
// ---------------------------------------------------------------------------
__global__ void __launch_bounds__(NTHREADS, 1)
attn_flash_kernel()
{
    extern __shared__ char smem[];
    const uint32_t smb = smem_u32_of(smem);
    const int tid  = threadIdx.x;
    const int lane = tid & 31;
    const int w    = tid >> 5;
    const int b    = blockIdx.x >> 4;
    const int yb   = blockIdx.x & 15;

    const uint4* xh = g_xhi + (size_t)b * SEQX * 16;
    const uint4* xl = g_xlo + (size_t)b * SEQX * 16;
    const uint4* yh = g_yhi + ((size_t)b * SEQY + yb * 128) * 16;
    const uint4* yl = g_ylo + ((size_t)b * SEQY + yb * 128) * 16;

    // prologue: Y (128 rows hi+lo) + X tile0, then X tile1
    {
        const int r  = tid >> 1;             // 0..127
        const int c0 = (tid & 1) * 8;
        const uint32_t dst = smb + OFF_Y + (uint32_t)r * PITCH + (uint32_t)c0 * 16u;
        const uint4* h = yh + r * 16 + c0;
        const uint4* l = yl + r * 16 + c0;
        #pragma unroll
        for (int c = 0; c < 8; ++c) {
            CP16(dst + c * 16u,           (const void*)(h + c));
            CP16(dst + c * 16u + DLT_YLO, (const void*)(l + c));
        }
    }
    load_xtile(smb + OFF_X0, xh, xl, tid);
    CPCOMMIT();
    load_xtile(smb + OFF_X1, xh + 64 * 16, xl + 64 * 16, tid);
    CPCOMMIT();

    // ldmatrix lane-address components
    const uint32_t aY = smb + OFF_Y +
        (uint32_t)(w * 16 + (lane & 15)) * PITCH + (uint32_t)(lane >> 4) * 16u;
    const uint32_t bs_row = (uint32_t)((lane & 7) + ((lane >> 4) << 3)) * PITCH +
                            (uint32_t)(((lane >> 3) & 1) << 4);
    const uint32_t pv_row = (uint32_t)((lane & 7) + (((lane >> 3) & 1) << 3)) * PITCH +
                            (uint32_t)((lane >> 4) << 4);

    float O[16][4];
    #pragma unroll
    for (int n = 0; n < 16; ++n)
        #pragma unroll
        for (int e = 0; e < 4; ++e) O[n][e] = 0.f;
    float rs0 = 0.f, rs1 = 0.f;

    for (int t = 0; t < NT; ++t) {
        CPWAIT1();                          // Y + tile t resident
        __syncthreads();
        const uint32_t XH = smb + ((t & 1) ? OFF_X1 : OFF_X0);

        // ---- S = Y(16) @ X(64)^T, 3-pass bf16 split, interleaved chains ----
        float S[8][4];
        #pragma unroll
        for (int n = 0; n < 8; ++n)
            #pragma unroll
            for (int e = 0; e < 4; ++e) S[n][e] = 0.f;

        #pragma unroll
        for (int ks = 0; ks < 8; ++ks) {
            uint32_t Ah[4], Al[4];
            LDSM4(Ah, aY + ks * 32);
            LDSM4(Al, aY + ks * 32 + DLT_YLO);
            #pragma unroll
            for (int qp = 0; qp < 2; ++qp) {
                uint32_t B0h[4], B1h[4], B0l[4], B1l[4];
                const uint32_t ba0 = XH + (uint32_t)(qp * 32) * PITCH + bs_row + ks * 32;
                const uint32_t ba1 = ba0 + 16 * PITCH;
                LDSM4(B0h, ba0);
                LDSM4(B1h, ba1);
                LDSM4(B0l, ba0 + DLT_XLO);
                LDSM4(B1l, ba1 + DLT_XLO);
                MMA(S[4*qp+0], Ah, B0h[0], B0h[1]);
                MMA(S[4*qp+1], Ah, B0h[2], B0h[3]);
                MMA(S[4*qp+2], Ah, B1h[0], B1h[1]);
                MMA(S[4*qp+3], Ah, B1h[2], B1h[3]);
                MMA(S[4*qp+0], Ah, B0l[0], B0l[1]);
                MMA(S[4*qp+1], Ah, B0l[2], B0l[3]);
                MMA(S[4*qp+2], Ah, B1l[0], B1l[1]);
                MMA(S[4*qp+3], Ah, B1l[2], B1l[3]);
                MMA(S[4*qp+0], Al, B0h[0], B0h[1]);
                MMA(S[4*qp+1], Al, B0h[2], B0h[3]);
                MMA(S[4*qp+2], Al, B1h[0], B1h[1]);
                MMA(S[4*qp+3], Al, B1h[2], B1h[3]);
            }
        }

        // ---- exp -> P hi/lo fragments, row-sum update ----
        uint32_t Phi[4][4], Plo[4][4];
        #pragma unroll
        for (int n = 0; n < 8; ++n) {
            float e0 = __expf(S[n][0]);
            float e1 = __expf(S[n][1]);
            float e2 = __expf(S[n][2]);
            float e3 = __expf(S[n][3]);
            rs0 += e0 + e1;
            rs1 += e2 + e3;
            const int j = n >> 1, h = n & 1;
            uint32_t p01 = pack_f2(e0, e1);
            uint32_t p23 = pack_f2(e2, e3);
            Phi[j][2*h]   = p01;
            Phi[j][2*h+1] = p23;
            float r0 = e0 - __uint_as_float(p01 << 16);
            float r1 = e1 - __uint_as_float(p01 & 0xffff0000u);
            float r2 = e2 - __uint_as_float(p23 << 16);
            float r3 = e3 - __uint_as_float(p23 & 0xffff0000u);
            Plo[j][2*h]   = pack_f2(r0, r1);
            Plo[j][2*h+1] = pack_f2(r2, r3);
        }

        // ---- O += Phi@Xhi + Phi@Xlo + Plo@Xhi, interleaved chains ----
        #pragma unroll
        for (int j = 0; j < 4; ++j) {
            #pragma unroll
            for (int qp = 0; qp < 4; ++qp) {
                uint32_t B0h[4], B1h[4], B0l[4], B1l[4];
                const uint32_t ba0 = XH + (uint32_t)(j * 16) * PITCH + pv_row + qp * 64;
                const uint32_t ba1 = ba0 + 32;
                LDSM4T(B0h, ba0);
                LDSM4T(B1h, ba1);
                LDSM4T(B0l, ba0 + DLT_XLO);
                LDSM4T(B1l, ba1 + DLT_XLO);
                MMA(O[4*qp+0], Phi[j], B0h[0], B0h[1]);
                MMA(O[4*qp+1], Phi[j], B0h[2], B0h[3]);
                MMA(O[4*qp+2], Phi[j], B1h[0], B1h[1]);
                MMA(O[4*qp+3], Phi[j], B1h[2], B1h[3]);
                MMA(O[4*qp+0], Phi[j], B0l[0], B0l[1]);
                MMA(O[4*qp+1], Phi[j], B0l[2], B0l[3]);
                MMA(O[4*qp+2], Phi[j], B1l[0], B1l[1]);
                MMA(O[4*qp+3], Phi[j], B1l[2], B1l[3]);
                MMA(O[4*qp+0], Plo[j], B0h[0], B0h[1]);
                MMA(O[4*qp+1], Plo[j], B0h[2], B0h[3]);
                MMA(O[4*qp+2], Plo[j], B1h[0], B1h[1]);
                MMA(O[4*qp+3], Plo[j], B1h[2], B1h[3]);
            }
        }
        __syncthreads();                    // buf(t) free
        if (t + 2 < NT) {
            load_xtile(smb + ((t & 1) ? OFF_X1 : OFF_X0),
                       xh + (size_t)(t + 2) * 64 * 16,
                       xl + (size_t)(t + 2) * 64 * 16, tid);
            CPCOMMIT();
        }
    }

    // ---- epilogue: per-warp sum_y O/l -> smem -> g_partial ----
    rs0 += __shfl_xor_sync(0xffffffffu, rs0, 1);
    rs0 += __shfl_xor_sync(0xffffffffu, rs0, 2);
    rs1 += __shfl_xor_sync(0xffffffffu, rs1, 1);
    rs1 += __shfl_xor_sync(0xffffffffu, rs1, 2);
    const float li0 = 1.0f / rs0;
    const float li1 = 1.0f / rs1;
    #pragma unroll
    for (int n = 0; n < 16; ++n) {
        float v0 = O[n][0] * li0 + O[n][2] * li1;
        float v1 = O[n][1] * li0 + O[n][3] * li1;
        v0 += __shfl_xor_sync(0xffffffffu, v0, 4);
        v0 += __shfl_xor_sync(0xffffffffu, v0, 8);
        v0 += __shfl_xor_sync(0xffffffffu, v0, 16);
        v1 += __shfl_xor_sync(0xffffffffu, v1, 4);
        v1 += __shfl_xor_sync(0xffffffffu, v1, 8);
        v1 += __shfl_xor_sync(0xffffffffu, v1, 16);
        if (lane < 4) {
            uint32_t ra = smb + OFF_RED + (uint32_t)(w * 128 + n * 8 + lane * 2) * 4;
            sts32(ra,     __float_as_uint(v0));
            sts32(ra + 4, __float_as_uint(v1));
        }
    }
    __syncthreads();
    if (tid < DIM) {
        float s = 0.f;
        #pragma unroll
        for (int ww = 0; ww < 8; ++ww)
            s += lds32f(smb + OFF_RED + (uint32_t)(ww * 128 + tid) * 4);
        g_partial[blockIdx.x * DIM + tid] = s;
    }
}

// ---------------------------------------------------------------------------
// visual path (exact fp32 rank-1)
// ---------------------------------------------------------------------------
__global__ void ysum_kernel(const float* __restrict__ Yg)
{
    __shared__ float buf[2 * DIM];
    int b = blockIdx.x;
    int d = threadIdx.x & 127;
    int h = threadIdx.x >> 7;
    const float* p = Yg + ((size_t)b * SEQY + h) * DIM + d;
    float s0 = 0.f, s1 = 0.f, s2 = 0.f, s3 = 0.f;
    for (int y = 0; y < SEQY / 2; y += 4) {
        s0 += p[(size_t)(2 * (y + 0)) * DIM];
        s1 += p[(size_t)(2 * (y + 1)) * DIM];
        s2 += p[(size_t)(2 * (y + 2)) * DIM];
        s3 += p[(size_t)(2 * (y + 3)) * DIM];
    }
    buf[h * DIM + d] = (s0 + s1) + (s2 + s3);
    __syncthreads();
    if (h == 0) g_ysum[b * DIM + d] = buf[d] + buf[DIM + d];
}

__global__ void visual_kernel(const float* __restrict__ Xg, float* __restrict__ out)
{
    __shared__ float ys[DIM];
    const int bpb = SEQX / 8;
    int b  = blockIdx.x / bpb;
    int x0 = (blockIdx.x % bpb) * 8;
    if (threadIdx.x < DIM) ys[threadIdx.x] = g_ysum[b * DIM + threadIdx.x];
    __syncthreads();
    int w    = threadIdx.x >> 5;
    int lane = threadIdx.x & 31;
    int x    = x0 + w;
    const float* xp = Xg + ((size_t)b * SEQX + x) * DIM + lane * 4;
    float4 xv = *reinterpret_cast<const float4*>(xp);
    float4 yv = *reinterpret_cast<const float4*>(ys + lane * 4);
    float sdot = xv.x * yv.x + xv.y * yv.y + xv.z * yv.z + xv.w * yv.w;
    #pragma unroll
    for (int o = 16; o > 0; o >>= 1)
        sdot += __shfl_xor_sync(0xffffffffu, sdot, o);
    if (lane == 0) out[(size_t)b * SEQX + x] = sdot * (1.0f / SEQY);
}

__global__ void outfinal_kernel(float* __restrict__ out)
{
    int b = blockIdx.x, d = threadIdx.x;
    float s = 0.f;
    #pragma unroll
    for (int g = 0; g < YB; ++g)
        s += g_partial[(b * YB + g) * DIM + d];
    out[(size_t)BATCH * SEQX + b * DIM + d] = s * (1.0f / SEQY);
}

extern "C" void kernel_launch(void* const* d_in, const int* in_sizes, int n_in,
                              void* d_out, int out_size)
{
    const float* X = (const float*)d_in[0];
    const float* Y = (const float*)d_in[1];
    float* out = (float*)d_out;
    (void)in_sizes; (void)n_in; (void)out_size;

    cudaFuncSetAttribute(attn_flash_kernel,
                         cudaFuncAttributeMaxDynamicSharedMemorySize, SM_BYTES);

    preconv_kernel<<<4096, 256>>>(X, Y);
    ysum_kernel<<<BATCH, 256>>>(Y);
    visual_kernel<<<BATCH * SEQX / 8, 256>>>(X, out);
    attn_flash_kernel<<<BATCH * YB, NTHREADS, SM_BYTES>>>();
    outfinal_kernel<<<BATCH, DIM>>>(out);
}